// round 4
// baseline (speedup 1.0000x reference)
#include <cuda_runtime.h>
#include <cstdint>

// Problem constants
static constexpr int B = 64;
static constexpr int T = 512;
static constexpr int D = 1024;
static constexpr int S = 1024;
static constexpr int U = 10;
static constexpr int NCH = 8;            // T-chunks (blocks per batch)
static constexpr int TCH = T / NCH;      // 64 t per block
static constexpr int NW  = 8;            // warps per block
static constexpr int G   = 4;            // t's per warp-group

// Scratch (device globals: no allocation allowed)
__device__ float g_cpart2[B * NCH * NW * D];   // per-warp context partials (16 MB)
__device__ float g_e[B * T];                   // exp(e) values

typedef unsigned long long ull;

// ---------- packed f32x2 helpers (sm_103a) ----------
static __device__ __forceinline__ ull pack2(float x, float y) {
    ull r;
    asm("mov.b64 %0, {%1, %2};" : "=l"(r) : "f"(x), "f"(y));
    return r;
}
static __device__ __forceinline__ float2 unpack2(ull v) {
    float2 r;
    asm("mov.b64 {%0, %1}, %2;" : "=f"(r.x), "=f"(r.y) : "l"(v));
    return r;
}
static __device__ __forceinline__ ull fma2(ull a, ull b, ull c) {
    ull d;
    asm("fma.rn.f32x2 %0, %1, %2, %3;" : "=l"(d) : "l"(a), "l"(b), "l"(c));
    return d;
}

// accurate-enough tanh via exp identity (~1e-6 rel)
static __device__ __forceinline__ float fast_tanh(float x) {
    float ex = __expf(2.0f * x);            // limits: 0 -> -1, inf -> +1, both fine
    return 1.0f - __fdividef(2.0f, ex + 1.0f);
}

// ---------- K1: fused u2 + e + max-free softmax numerator + context partials ----------
// grid (NCH, B), 256 threads = 8 warps. Warp w owns t = ch*64 + w*8 + {0..7}.
// No cross-warp coupling in steady state; a streamed once from DRAM (+L1 reread).
__global__ void __launch_bounds__(256, 2)
k1_main(const float* __restrict__ a,  const float* __restrict__ sp,
        const float* __restrict__ W1, const float* __restrict__ W2v,
        const float* __restrict__ b1, const float* __restrict__ b2) {
    const int ch = blockIdx.x, b = blockIdx.y;
    const int tid = threadIdx.x, w = tid >> 5, lane = tid & 31;

    __shared__ float ws[U][D];        // W1 front half, transposed (40 KB)
    __shared__ float red[NW][U];
    __shared__ float u2s[U], w2s[U];
    __shared__ float b2s;

    // ---- phase 0: transpose W1[:D] into smem; compute u2[b] inline ----
    {
        const int d0 = 4 * tid;
        float tmp[4][U];
#pragma unroll
        for (int j = 0; j < 4; j++) {
            const float2* r = reinterpret_cast<const float2*>(W1 + (size_t)(d0 + j) * U);
#pragma unroll
            for (int k = 0; k < 5; k++) {
                float2 v = r[k];
                tmp[j][2 * k] = v.x; tmp[j][2 * k + 1] = v.y;
            }
        }
#pragma unroll
        for (int u = 0; u < U; u++)
#pragma unroll
            for (int j = 0; j < 4; j++) ws[u][d0 + j] = tmp[j][u];

        // u2 partial: s_prev[b] @ W1[D:, u]
        float4 s4 = *reinterpret_cast<const float4*>(sp + (size_t)b * S + d0);
        float sj[4] = {s4.x, s4.y, s4.z, s4.w};
        float p[U];
#pragma unroll
        for (int u = 0; u < U; u++) p[u] = 0.0f;
#pragma unroll
        for (int j = 0; j < 4; j++) {
            const float2* r = reinterpret_cast<const float2*>(W1 + (size_t)(D + d0 + j) * U);
#pragma unroll
            for (int k = 0; k < 5; k++) {
                float2 v = r[k];
                p[2 * k]     += sj[j] * v.x;
                p[2 * k + 1] += sj[j] * v.y;
            }
        }
#pragma unroll
        for (int off = 16; off; off >>= 1)
#pragma unroll
            for (int u = 0; u < U; u++) p[u] += __shfl_xor_sync(0xffffffffu, p[u], off);
        if (lane == 0) {
#pragma unroll
            for (int u = 0; u < U; u++) red[w][u] = p[u];
        }
    }
    __syncthreads();
    if (tid < U) {
        float s = 0.0f;
#pragma unroll
        for (int k = 0; k < NW; k++) s += red[k][tid];
        u2s[tid] = s + b1[tid];
        w2s[tid] = W2v[tid];
    }
    if (tid == 0) b2s = b2[0];
    __syncthreads();     // last barrier — steady state below is barrier-free

    // ---- main: per-warp, 2 groups of G=4 timesteps ----
    const int tbase = ch * TCH + w * 8;
    const float* aw = a + ((size_t)b * T + tbase) * D + lane * 4;

    ull c01[8], c23[8];               // context accumulator: d = p*128 + lane*4 + {0..3}
#pragma unroll
    for (int p = 0; p < 8; p++) { c01[p] = 0ull; c23[p] = 0ull; }

    for (int grp = 0; grp < 2; grp++) {
        const float* ab = aw + (size_t)grp * G * D;

        ull a01[G], a23[G];
        float4 anx[G];
#pragma unroll
        for (int g = 0; g < G; g++) {
            float4 v = *reinterpret_cast<const float4*>(ab + (size_t)g * D);
            a01[g] = pack2(v.x, v.y); a23[g] = pack2(v.z, v.w);
        }

        float acc[G][U];
#pragma unroll
        for (int g = 0; g < G; g++)
#pragma unroll
            for (int u = 0; u < U; u++) acc[g][u] = 0.0f;

#pragma unroll
        for (int p = 0; p < 8; p++) {
            if (p < 7) {
#pragma unroll
                for (int g = 0; g < G; g++)
                    anx[g] = *reinterpret_cast<const float4*>(ab + (size_t)g * D + (p + 1) * 128);
            }
#pragma unroll
            for (int u = 0; u < U; u++) {
                float4 wq = *reinterpret_cast<const float4*>(&ws[u][p * 128 + lane * 4]);
                ull w01 = pack2(wq.x, wq.y), w23 = pack2(wq.z, wq.w);
#pragma unroll
                for (int g = 0; g < G; g++) {
                    // acc folded into the packed-fma chain seed: 3 fma-pipe slots per (g,u)
                    ull q = fma2(a01[g], w01, fma2(a23[g], w23, pack2(acc[g][u], 0.0f)));
                    float2 f = unpack2(q);
                    acc[g][u] = f.x + f.y;
                }
            }
            if (p < 7) {
#pragma unroll
                for (int g = 0; g < G; g++) {
                    a01[g] = pack2(anx[g].x, anx[g].y);
                    a23[g] = pack2(anx[g].z, anx[g].w);
                }
            }
        }

        // 32-lane butterfly reduce, 40 independent chains interleaved (latency hidden)
#pragma unroll
        for (int off = 16; off; off >>= 1)
#pragma unroll
            for (int g = 0; g < G; g++)
#pragma unroll
                for (int u = 0; u < U; u++)
                    acc[g][u] += __shfl_xor_sync(0xffffffffu, acc[g][u], off);

        // e -> relu -> exp (max-free: e in [0, ~3])
        float ex[G];
#pragma unroll
        for (int g = 0; g < G; g++) {
            float e = b2s;
#pragma unroll
            for (int u = 0; u < U; u++) e += w2s[u] * fast_tanh(acc[g][u] + u2s[u]);
            e = fmaxf(e, 0.0f);
            ex[g] = __expf(e);
        }
        if (lane == 0) {
            *reinterpret_cast<float4*>(&g_e[b * T + tbase + grp * G]) =
                make_float4(ex[0], ex[1], ex[2], ex[3]);
        }

        // context accumulation: reread a (L1-hot 16KB window), register-resident ctx
#pragma unroll
        for (int g = 0; g < G; g++) {
            ull eg = pack2(ex[g], ex[g]);
#pragma unroll
            for (int p = 0; p < 8; p++) {
                float4 v = *reinterpret_cast<const float4*>(ab + (size_t)g * D + p * 128);
                c01[p] = fma2(eg, pack2(v.x, v.y), c01[p]);
                c23[p] = fma2(eg, pack2(v.z, v.w), c23[p]);
            }
        }
    }

    // store per-warp context partial
    float* cb = g_cpart2 + (((size_t)(b * NCH + ch)) * NW + w) * D + lane * 4;
#pragma unroll
    for (int p = 0; p < 8; p++) {
        float2 lo = unpack2(c01[p]), hi = unpack2(c23[p]);
        *reinterpret_cast<float4*>(cb + p * 128) = make_float4(lo.x, lo.y, hi.x, hi.y);
    }
}

// ---------- K2: combine 64 per-warp partials, normalize, write outputs ----------
__global__ void k2_combine(float* __restrict__ out, int scoreOff, int doScores) {
    int b = blockIdx.x;
    int tid = threadIdx.x;
    __shared__ float redz[8];
    __shared__ float zsh;

    float e0 = g_e[b * T + tid];
    float e1 = g_e[b * T + 256 + tid];
    float s = e0 + e1;
#pragma unroll
    for (int off = 16; off; off >>= 1) s += __shfl_xor_sync(0xffffffffu, s, off);
    if ((tid & 31) == 0) redz[tid >> 5] = s;
    __syncthreads();
    if (tid == 0) {
        float z = 0.0f;
#pragma unroll
        for (int k = 0; k < 8; k++) z += redz[k];
        zsh = 1.0f / z;        // z >= 512, safe
    }
    __syncthreads();
    float invZ = zsh;

    if (doScores) {
        out[scoreOff + b * T + tid]       = e0 * invZ;
        out[scoreOff + b * T + 256 + tid] = e1 * invZ;
    }

    float4 c = make_float4(0.f, 0.f, 0.f, 0.f);
    const float* cp = g_cpart2 + ((size_t)b * NCH * NW) * D + 4 * tid;
#pragma unroll 8
    for (int k = 0; k < NCH * NW; k++) {
        float4 v = *reinterpret_cast<const float4*>(cp + (size_t)k * D);
        c.x += v.x; c.y += v.y; c.z += v.z; c.w += v.w;
    }
    c.x *= invZ; c.y *= invZ; c.z *= invZ; c.w *= invZ;
    *reinterpret_cast<float4*>(out + (size_t)b * D + 4 * tid) = c;
}

extern "C" void kernel_launch(void* const* d_in, const int* in_sizes, int n_in,
                              void* d_out, int out_size) {
    const float* a   = (const float*)d_in[0];   // [B,T,D]
    const float* sp  = (const float*)d_in[1];   // [B,S]
    const float* W1  = (const float*)d_in[2];   // [D+S, 10]
    const float* b1  = (const float*)d_in[3];   // [10]
    const float* W2  = (const float*)d_in[4];   // [10, 1]
    const float* b2  = (const float*)d_in[5];   // [1]
    float* out = (float*)d_out;

    int scoreOff = B * D;
    int doScores = (out_size >= B * D + B * T) ? 1 : 0;

    k1_main<<<dim3(NCH, B), 256>>>(a, sp, W1, W2, b1, b2);
    k2_combine<<<B, 256>>>(out, scoreOff, doScores);
}

// round 7
// speedup vs baseline: 3.1206x; 3.1206x over previous
#include <cuda_runtime.h>
#include <cstdint>

// Problem constants
static constexpr int B = 64, T = 512, D = 1024, S = 1024, U = 10;
static constexpr int CT   = 32;          // timesteps per block
static constexpr int NCHK = T / CT;      // 16 chunks per batch

// Scratch (device globals: no allocation allowed)
__device__ float g_cpart[B * NCHK * D];  // per-block context partials (4 MB)
__device__ float g_e[B * T];             // exp(e)

typedef unsigned long long ull;

// ---------- packed f32x2 helpers (sm_103a) ----------
static __device__ __forceinline__ ull pack2(float x, float y) {
    ull r; asm("mov.b64 %0, {%1, %2};" : "=l"(r) : "f"(x), "f"(y)); return r;
}
static __device__ __forceinline__ float2 unpack2(ull v) {
    float2 r; asm("mov.b64 {%0, %1}, %2;" : "=f"(r.x), "=f"(r.y) : "l"(v)); return r;
}
static __device__ __forceinline__ ull fma2(ull a, ull b, ull c) {
    ull d; asm("fma.rn.f32x2 %0, %1, %2, %3;" : "=l"(d) : "l"(a), "l"(b), "l"(c)); return d;
}
// accurate tanh via exp identity (~1e-6 rel)
static __device__ __forceinline__ float fast_tanh(float x) {
    float ex = __expf(2.0f * x);
    return 1.0f - __fdividef(2.0f, ex + 1.0f);
}
static __device__ __forceinline__ void pf_l2(const void* p) {
    asm volatile("prefetch.global.L2 [%0];" :: "l"(p));
}

// ---------- K1: fused u2 + e + max-free softmax numerator + context ----------
// grid (NCHK, B), 256 threads = 8 warps = 4 pairs. Pair owns 8 t; warps split d.
__global__ void __launch_bounds__(256, 2)
k1_main(const float* __restrict__ a,  const float* __restrict__ sp,
        const float* __restrict__ W1, const float* __restrict__ W2v,
        const float* __restrict__ b1, const float* __restrict__ b2) {
    const int ch = blockIdx.x, b = blockIdx.y;
    const int tid = threadIdx.x, w = tid >> 5, lane = tid & 31;
    const int side = w & 1, pair = w >> 1;

    __shared__ float ws[U][D];            // W1 front, transposed (40 KB)
    __shared__ float red[8][U];
    __shared__ float u2s[U], w2s[U];
    __shared__ float b2s;
    __shared__ __align__(16) float pairbuf[2][4][2][20];  // [grp parity][pair][side][t2*10+u]

    // ---- phase 0: transpose W1[:D] into smem; u2[b] inline ----
    {
        const int d0 = 4 * tid;
        float tmp[4][U];
#pragma unroll
        for (int j = 0; j < 4; j++) {
            const float2* r = reinterpret_cast<const float2*>(W1 + (size_t)(d0 + j) * U);
#pragma unroll
            for (int k = 0; k < 5; k++) {
                float2 v = r[k];
                tmp[j][2 * k] = v.x; tmp[j][2 * k + 1] = v.y;
            }
        }
#pragma unroll
        for (int u = 0; u < U; u++)
#pragma unroll
            for (int j = 0; j < 4; j++) ws[u][d0 + j] = tmp[j][u];

        float4 s4 = *reinterpret_cast<const float4*>(sp + (size_t)b * S + d0);
        float sj[4] = {s4.x, s4.y, s4.z, s4.w};
        float p[U];
#pragma unroll
        for (int u = 0; u < U; u++) p[u] = 0.0f;
#pragma unroll
        for (int j = 0; j < 4; j++) {
            const float2* r = reinterpret_cast<const float2*>(W1 + (size_t)(D + d0 + j) * U);
#pragma unroll
            for (int k = 0; k < 5; k++) {
                float2 v = r[k];
                p[2 * k]     += sj[j] * v.x;
                p[2 * k + 1] += sj[j] * v.y;
            }
        }
#pragma unroll
        for (int off = 16; off; off >>= 1)
#pragma unroll
            for (int u = 0; u < U; u++) p[u] += __shfl_xor_sync(0xffffffffu, p[u], off);
        if (lane == 0) {
#pragma unroll
            for (int u = 0; u < U; u++) red[w][u] = p[u];
        }
    }

    // warp's base pointer for its d-half; prefetch group 0 into L2 during phase-0 sync
    const int tbase = ch * CT + pair * 8;
    const float* awp = a + ((size_t)(b * T + tbase)) * D + side * 512 + lane * 4;
#pragma unroll
    for (int p = 0; p < 4; p++) {
        pf_l2(awp + p * 128);
        pf_l2(awp + D + p * 128);
    }

    __syncthreads();
    if (tid < U) {
        float s = 0.0f;
#pragma unroll
        for (int k = 0; k < 8; k++) s += red[k][tid];
        u2s[tid] = s + b1[tid];
        w2s[tid] = W2v[tid];
    }
    if (tid == 0) b2s = b2[0];
    __syncthreads();

    // ---- main: 4 groups of 2 t per pair; only named barriers (1/group) ----
    ull c01[4] = {0ull, 0ull, 0ull, 0ull}, c23[4] = {0ull, 0ull, 0ull, 0ull};

    for (int grp = 0; grp < 4; grp++) {
        const float* at0 = awp + (size_t)(grp * 2) * D;

        if (grp < 3) {                 // warm next group's lines in L2 (no regs)
            const float* nf = at0 + 2 * D;
#pragma unroll
            for (int p = 0; p < 4; p++) {
                pf_l2(nf + p * 128);
                pf_l2(nf + D + p * 128);
            }
        }

        // packed accumulators; u2+b1 seeded once (lane 0 of side 0 only!)
        ull acc0[U], acc1[U];
#pragma unroll
        for (int u = 0; u < U; u++) {
            float seed = (side == 0 && lane == 0) ? u2s[u] : 0.0f;
            acc0[u] = pack2(seed, 0.0f);
            acc1[u] = pack2(seed, 0.0f);
        }

        float4 av0 = *reinterpret_cast<const float4*>(at0);
        float4 av1 = *reinterpret_cast<const float4*>(at0 + D);
#pragma unroll
        for (int p = 0; p < 4; p++) {
            float4 n0, n1;
            if (p < 3) {
                n0 = *reinterpret_cast<const float4*>(at0 + (p + 1) * 128);
                n1 = *reinterpret_cast<const float4*>(at0 + D + (p + 1) * 128);
            }
            ull a001 = pack2(av0.x, av0.y), a023 = pack2(av0.z, av0.w);
            ull a101 = pack2(av1.x, av1.y), a123 = pack2(av1.z, av1.w);
            const int wb = side * 512 + p * 128 + lane * 4;
#pragma unroll
            for (int u = 0; u < U; u++) {
                float4 wq = *reinterpret_cast<const float4*>(&ws[u][wb]);
                ull w01 = pack2(wq.x, wq.y), w23 = pack2(wq.z, wq.w);
                acc0[u] = fma2(a001, w01, fma2(a023, w23, acc0[u]));
                acc1[u] = fma2(a101, w01, fma2(a123, w23, acc1[u]));
            }
            if (p < 3) { av0 = n0; av1 = n1; }
        }

        // unpack once, then 32-lane butterfly (20 interleaved chains)
        float s0[U], s1[U];
#pragma unroll
        for (int u = 0; u < U; u++) {
            float2 f = unpack2(acc0[u]); s0[u] = f.x + f.y;
            f = unpack2(acc1[u]);        s1[u] = f.x + f.y;
        }
#pragma unroll
        for (int off = 16; off; off >>= 1)
#pragma unroll
            for (int u = 0; u < U; u++) {
                s0[u] += __shfl_xor_sync(0xffffffffu, s0[u], off);
                s1[u] += __shfl_xor_sync(0xffffffffu, s1[u], off);
            }

        // exchange halves within pair (double-buffered by group parity)
        float* pb = &pairbuf[grp & 1][pair][side][0];
        if (lane == 0) {
            reinterpret_cast<float4*>(pb)[0] = make_float4(s0[0], s0[1], s0[2], s0[3]);
            reinterpret_cast<float4*>(pb)[1] = make_float4(s0[4], s0[5], s0[6], s0[7]);
            reinterpret_cast<float4*>(pb)[2] = make_float4(s0[8], s0[9], s1[0], s1[1]);
            reinterpret_cast<float4*>(pb)[3] = make_float4(s1[2], s1[3], s1[4], s1[5]);
            reinterpret_cast<float4*>(pb)[4] = make_float4(s1[6], s1[7], s1[8], s1[9]);
        }
        asm volatile("bar.sync %0, 64;" :: "r"(1 + pair) : "memory");
        const float* po = &pairbuf[grp & 1][pair][side ^ 1][0];

        // e -> relu -> exp (both warps redundantly; max-free since e in [0,~3])
        float e0 = b2s, e1 = b2s;
#pragma unroll
        for (int u = 0; u < U; u++) {
            e0 += w2s[u] * fast_tanh(s0[u] + po[u]);
            e1 += w2s[u] * fast_tanh(s1[u] + po[10 + u]);
        }
        float ex0 = __expf(fmaxf(e0, 0.0f));
        float ex1 = __expf(fmaxf(e1, 0.0f));
        if (side == 0 && lane == 0)
            *reinterpret_cast<float2*>(&g_e[b * T + tbase + grp * 2]) = make_float2(ex0, ex1);

        // context accumulation: reread group window (L1-hot)
        ull E0 = pack2(ex0, ex0), E1 = pack2(ex1, ex1);
#pragma unroll
        for (int p = 0; p < 4; p++) {
            float4 r0 = *reinterpret_cast<const float4*>(at0 + p * 128);
            float4 r1 = *reinterpret_cast<const float4*>(at0 + D + p * 128);
            c01[p] = fma2(E0, pack2(r0.x, r0.y), c01[p]);
            c23[p] = fma2(E0, pack2(r0.z, r0.w), c23[p]);
            c01[p] = fma2(E1, pack2(r1.x, r1.y), c01[p]);
            c23[p] = fma2(E1, pack2(r1.z, r1.w), c23[p]);
        }
    }

    // ---- block-level ctx combine (reuse ws smem), one global write per d ----
    __syncthreads();
    float* cbuf = &ws[0][0];                 // 4 pairs x 1024 d = 16 KB
#pragma unroll
    for (int p = 0; p < 4; p++) {
        float2 lo = unpack2(c01[p]), hi = unpack2(c23[p]);
        *reinterpret_cast<float4*>(&cbuf[pair * D + side * 512 + p * 128 + lane * 4]) =
            make_float4(lo.x, lo.y, hi.x, hi.y);
    }
    __syncthreads();
    {
        const int d0 = 4 * tid;
        float4 cs = make_float4(0.f, 0.f, 0.f, 0.f);
#pragma unroll
        for (int q = 0; q < 4; q++) {
            float4 v = *reinterpret_cast<const float4*>(&cbuf[q * D + d0]);
            cs.x += v.x; cs.y += v.y; cs.z += v.z; cs.w += v.w;
        }
        *reinterpret_cast<float4*>(&g_cpart[((size_t)(b * NCHK + ch)) * D + d0]) = cs;
    }
}

// ---------- K2: combine 16 chunk partials, normalize, write outputs ----------
// 256 blocks: 4 d-quarters per batch; z computed redundantly per block.
__global__ void k2_combine(float* __restrict__ out, int scoreOff, int doScores) {
    int bq = blockIdx.x;
    int b = bq >> 2, dq = bq & 3;
    int tid = threadIdx.x;
    __shared__ float redz[8];
    __shared__ float zsh;

    float e0 = g_e[b * T + tid];
    float e1 = g_e[b * T + 256 + tid];
    float s = e0 + e1;
#pragma unroll
    for (int off = 16; off; off >>= 1) s += __shfl_xor_sync(0xffffffffu, s, off);
    if ((tid & 31) == 0) redz[tid >> 5] = s;
    __syncthreads();
    if (tid == 0) {
        float z = 0.0f;
#pragma unroll
        for (int k = 0; k < 8; k++) z += redz[k];
        zsh = 1.0f / z;              // z >= 512 (e >= 0), safe
    }
    __syncthreads();
    float invZ = zsh;

    if (dq == 0 && doScores) {
        out[scoreOff + b * T + tid]       = e0 * invZ;
        out[scoreOff + b * T + 256 + tid] = e1 * invZ;
    }

    int d = dq * 256 + tid;
    float c = 0.0f;
#pragma unroll
    for (int chn = 0; chn < NCHK; chn++)
        c += g_cpart[((size_t)(b * NCHK + chn)) * D + d];
    out[(size_t)b * D + d] = c * invZ;
}

extern "C" void kernel_launch(void* const* d_in, const int* in_sizes, int n_in,
                              void* d_out, int out_size) {
    const float* a   = (const float*)d_in[0];   // [B,T,D]
    const float* sp  = (const float*)d_in[1];   // [B,S]
    const float* W1  = (const float*)d_in[2];   // [D+S, 10]
    const float* b1  = (const float*)d_in[3];   // [10]
    const float* W2  = (const float*)d_in[4];   // [10, 1]
    const float* b2  = (const float*)d_in[5];   // [1]
    float* out = (float*)d_out;

    int scoreOff = B * D;
    int doScores = (out_size >= B * D + B * T) ? 1 : 0;

    k1_main<<<dim3(NCHK, B), 256>>>(a, sp, W1, W2, b1, b2);
    k2_combine<<<4 * B, 256>>>(out, scoreOff, doScores);
}